// round 2
// baseline (speedup 1.0000x reference)
#include <cuda_runtime.h>
#include <math.h>

#define NB 32
#define NT 1024
#define NE 256
#define NH 4
#define NHD 64
#define NP 32
#define NM (NB*NT)

typedef unsigned long long ull;

// ---- packed fp32x2 helpers (FFMA2 path; ptxas never emits these from C++) ----
__device__ __forceinline__ void ffma2(ull& d, ull a, ull b) {
    asm("fma.rn.f32x2 %0, %1, %2, %3;" : "=l"(d) : "l"(a), "l"(b), "l"(d));
}
__device__ __forceinline__ ull mul2(ull a, ull b) {
    ull r; asm("mul.rn.f32x2 %0, %1, %2;" : "=l"(r) : "l"(a), "l"(b)); return r;
}
__device__ __forceinline__ ull pack2(float lo, float hi) {
    ull r; asm("mov.b64 %0, {%1, %2};" : "=l"(r) : "f"(lo), "f"(hi)); return r;
}
__device__ __forceinline__ float2 unpack2(ull v) {
    float2 f; asm("mov.b64 {%0, %1}, %2;" : "=f"(f.x), "=f"(f.y) : "l"(v)); return f;
}

// ---- scratch (static device globals; no runtime allocation) ----
__device__ float g_h  [(size_t)NM*NE];
__device__ float g_qkv[(size_t)NM*3*NE];
__device__ float g_ctx[(size_t)NM*NE];
__device__ float g_ao [(size_t)NM*NE];
__device__ float g_bs [NM];
__device__ int   g_pid[NM];
__device__ float g_pe [NB*NP*NE];

// ============================================================================
// C[M,N] = A[M,K] @ W[N,K]^T + bias    (M%128==0, N%128==0, K%16==0)
// 128x128 tile, BK=16, 256 threads, 8x8 per thread via fp32x2 FFMA2.
// A is stored DUPLICATED in smem (As2[k][2m] twice) so broadcast pairs load
// directly with LDS.128 -- no pack MOVs in the inner loop.
// ============================================================================
__global__ __launch_bounds__(256, 2) void gemm_bias_kernel(
    const float* __restrict__ A, const float* __restrict__ W,
    const float* __restrict__ bias, float* __restrict__ C,
    int Ndim, int Kdim)
{
    __shared__ float As2[16][256];   // [k][2*m] duplicated pairs (16KB)
    __shared__ float Bs [16][132];   // [k][n] (+pad)             (8.25KB)

    const int tid = threadIdx.x;
    const int tx = tid & 15, ty = tid >> 4;
    const int bm = blockIdx.y << 7;
    const int bn = blockIdx.x << 7;
    const int lr = tid >> 1;             // 0..127
    const int lk = (tid & 1) << 3;       // 0 or 8

    ull acc[8][4];
#pragma unroll
    for (int i = 0; i < 8; i++)
#pragma unroll
        for (int j = 0; j < 4; j++) acc[i][j] = 0ull;

    const float* Ap = A + (size_t)(bm + lr) * Kdim + lk;
    const float* Wp = W + (size_t)(bn + lr) * Kdim + lk;

    for (int k0 = 0; k0 < Kdim; k0 += 16) {
        __syncthreads();
#pragma unroll
        for (int half = 0; half < 2; half++) {
            float4 a = *(const float4*)(Ap + k0 + half*4);
            float4 w = *(const float4*)(Wp + k0 + half*4);
            int kb = lk + half*4;
            *(ull*)&As2[kb+0][2*lr] = pack2(a.x, a.x);
            *(ull*)&As2[kb+1][2*lr] = pack2(a.y, a.y);
            *(ull*)&As2[kb+2][2*lr] = pack2(a.z, a.z);
            *(ull*)&As2[kb+3][2*lr] = pack2(a.w, a.w);
            Bs[kb+0][lr] = w.x; Bs[kb+1][lr] = w.y;
            Bs[kb+2][lr] = w.z; Bs[kb+3][lr] = w.w;
        }
        __syncthreads();
#pragma unroll
        for (int kk = 0; kk < 16; kk++) {
            const float* Ak = &As2[kk][0];
            const float* Bk = &Bs[kk][0];
            ulonglong2 a01 = *(const ulonglong2*)(Ak + 8*ty);
            ulonglong2 a23 = *(const ulonglong2*)(Ak + 8*ty + 4);
            ulonglong2 a45 = *(const ulonglong2*)(Ak + 128 + 8*ty);
            ulonglong2 a67 = *(const ulonglong2*)(Ak + 128 + 8*ty + 4);
            ulonglong2 b01 = *(const ulonglong2*)(Bk + 4*tx);
            ulonglong2 b23 = *(const ulonglong2*)(Bk + 64 + 4*tx);
            ull av[8] = {a01.x, a01.y, a23.x, a23.y, a45.x, a45.y, a67.x, a67.y};
            ull bv[4] = {b01.x, b01.y, b23.x, b23.y};
#pragma unroll
            for (int i = 0; i < 8; i++)
#pragma unroll
                for (int j = 0; j < 4; j++) ffma2(acc[i][j], av[i], bv[j]);
        }
    }

    float4 bb0 = *(const float4*)(bias + bn + 4*tx);
    float4 bb1 = *(const float4*)(bias + bn + 64 + 4*tx);
#pragma unroll
    for (int ii = 0; ii < 8; ii++) {
        int row = bm + ((ii < 4) ? (4*ty + ii) : (64 + 4*ty + ii - 4));
        float2 c0 = unpack2(acc[ii][0]);
        float2 c1 = unpack2(acc[ii][1]);
        float2 c2 = unpack2(acc[ii][2]);
        float2 c3 = unpack2(acc[ii][3]);
        float* cp = C + (size_t)row * Ndim;
        *(float4*)(cp + bn + 4*tx) =
            make_float4(c0.x+bb0.x, c0.y+bb0.y, c1.x+bb0.z, c1.y+bb0.w);
        *(float4*)(cp + bn + 64 + 4*tx) =
            make_float4(c2.x+bb1.x, c2.y+bb1.y, c3.x+bb1.z, c3.y+bb1.w);
    }
}

// ============================================================================
// Flash attention, fp32 with FFMA2. One block = one (b,h) x 64 query rows.
// BQ=64, BKV=32, HD=64, 256 threads (16x16). ~44KB static smem.
// Q and P stored transposed so consecutive q-rows form natural f32x2 pairs.
// ============================================================================
__global__ __launch_bounds__(256) void flash_kernel(
    const float* __restrict__ qkv, float* __restrict__ ctx)
{
    __shared__ float QsT[64][68];   // [d][qrow]  (prescaled by 0.125)
    __shared__ float KsT[64][36];   // [d][key]
    __shared__ float Vs [32][68];   // [key][d]
    __shared__ float PsT[32][68];   // [key][qrow]

    const int tid = threadIdx.x;
    const int tx = tid & 15, ty = tid >> 4;
    const int qb = blockIdx.x;
    const int bh = blockIdx.y;
    const int b = bh >> 2, h = bh & 3;

    const float* base = qkv + (size_t)b * NT * (3*NE);
    const int qoff = h * NHD;
    const int koff = NE + h * NHD;
    const int voff = 2*NE + h * NHD;
    const int qstart = qb << 6;

    // load Q transposed + prescaled
#pragma unroll
    for (int it = 0; it < 4; it++) {
        int idx = it*256 + tid;
        int r  = idx >> 4;
        int c4 = (idx & 15) << 2;
        float4 v = *(const float4*)(base + (size_t)(qstart + r)*(3*NE) + qoff + c4);
        QsT[c4+0][r] = v.x*0.125f; QsT[c4+1][r] = v.y*0.125f;
        QsT[c4+2][r] = v.z*0.125f; QsT[c4+3][r] = v.w*0.125f;
    }

    float m[4], l[4];
    ull acc_o[2][4];
#pragma unroll
    for (int i = 0; i < 4; i++) { m[i] = -1e30f; l[i] = 0.f; }
#pragma unroll
    for (int rp = 0; rp < 2; rp++)
#pragma unroll
        for (int j = 0; j < 4; j++) acc_o[rp][j] = 0ull;

    for (int kb = 0; kb < 32; kb++) {
        __syncthreads();
        // load K (transposed) and V tiles: 32 keys x 64 d
#pragma unroll
        for (int it = 0; it < 2; it++) {
            int idx = it*256 + tid;
            int r  = idx >> 4;
            int c4 = (idx & 15) << 2;
            size_t ra = (size_t)(kb*32 + r) * (3*NE);
            float4 kv = *(const float4*)(base + ra + koff + c4);
            KsT[c4+0][r]=kv.x; KsT[c4+1][r]=kv.y; KsT[c4+2][r]=kv.z; KsT[c4+3][r]=kv.w;
            *(float4*)&Vs[r][c4] = *(const float4*)(base + ra + voff + c4);
        }
        __syncthreads();

        // S = Q K^T : row-pairs (4ty+2rp,+1) x keys (2tx, 2tx+1)
        ull s00 = 0ull, s01 = 0ull, s10 = 0ull, s11 = 0ull;
#pragma unroll 16
        for (int d = 0; d < 64; d++) {
            ulonglong2 qp = *(const ulonglong2*)&QsT[d][4*ty];
            float2 kf = *(const float2*)&KsT[d][2*tx];
            ull kb0 = pack2(kf.x, kf.x);
            ull kb1 = pack2(kf.y, kf.y);
            ffma2(s00, qp.x, kb0); ffma2(s01, qp.x, kb1);
            ffma2(s10, qp.y, kb0); ffma2(s11, qp.y, kb1);
        }
        float sv[4][2];
        { float2 t = unpack2(s00); sv[0][0]=t.x; sv[1][0]=t.y; }
        { float2 t = unpack2(s01); sv[0][1]=t.x; sv[1][1]=t.y; }
        { float2 t = unpack2(s10); sv[2][0]=t.x; sv[3][0]=t.y; }
        { float2 t = unpack2(s11); sv[2][1]=t.x; sv[3][1]=t.y; }

        // online softmax (16 tx lanes hold the 32 keys of this tile)
        float corr[4];
#pragma unroll
        for (int i = 0; i < 4; i++) {
            float mx = fmaxf(sv[i][0], sv[i][1]);
#pragma unroll
            for (int off = 1; off < 16; off <<= 1)
                mx = fmaxf(mx, __shfl_xor_sync(0xffffffffu, mx, off));
            float mnew = fmaxf(m[i], mx);
            corr[i] = __expf(m[i] - mnew);
            float p0 = __expf(sv[i][0] - mnew);
            float p1 = __expf(sv[i][1] - mnew);
            float ls = p0 + p1;
#pragma unroll
            for (int off = 1; off < 16; off <<= 1)
                ls += __shfl_xor_sync(0xffffffffu, ls, off);
            l[i] = l[i]*corr[i] + ls;
            m[i] = mnew;
            PsT[2*tx  ][4*ty + i] = p0;
            PsT[2*tx+1][4*ty + i] = p1;
        }
        {
            ull c01 = pack2(corr[0], corr[1]);
            ull c23 = pack2(corr[2], corr[3]);
#pragma unroll
            for (int j = 0; j < 4; j++) {
                acc_o[0][j] = mul2(acc_o[0][j], c01);
                acc_o[1][j] = mul2(acc_o[1][j], c23);
            }
        }
        __syncthreads();

        // O += P @ V : row-pairs x d-cols (4tx..4tx+3)
#pragma unroll 8
        for (int kk = 0; kk < 32; kk++) {
            ulonglong2 pp = *(const ulonglong2*)&PsT[kk][4*ty];
            float4 vv = *(const float4*)&Vs[kk][4*tx];
            ull vb0 = pack2(vv.x, vv.x), vb1 = pack2(vv.y, vv.y);
            ull vb2 = pack2(vv.z, vv.z), vb3 = pack2(vv.w, vv.w);
            ffma2(acc_o[0][0], pp.x, vb0); ffma2(acc_o[0][1], pp.x, vb1);
            ffma2(acc_o[0][2], pp.x, vb2); ffma2(acc_o[0][3], pp.x, vb3);
            ffma2(acc_o[1][0], pp.y, vb0); ffma2(acc_o[1][1], pp.y, vb1);
            ffma2(acc_o[1][2], pp.y, vb2); ffma2(acc_o[1][3], pp.y, vb3);
        }
    }

#pragma unroll
    for (int rp = 0; rp < 2; rp++) {
        float2 u0 = unpack2(acc_o[rp][0]);
        float2 u1 = unpack2(acc_o[rp][1]);
        float2 u2 = unpack2(acc_o[rp][2]);
        float2 u3 = unpack2(acc_o[rp][3]);
        int r0 = 4*ty + 2*rp;
        float inv0 = 1.f / l[2*rp];
        float inv1 = 1.f / l[2*rp + 1];
        float* o0 = ctx + ((size_t)(b*NT) + qstart + r0) * NE + h*NHD + 4*tx;
        float* o1 = o0 + NE;
        *(float4*)o0 = make_float4(u0.x*inv0, u1.x*inv0, u2.x*inv0, u3.x*inv0);
        *(float4*)o1 = make_float4(u0.y*inv1, u1.y*inv1, u2.y*inv1, u3.y*inv1);
    }
}

// ============================================================================
// Boundary MLP: one warp per row, lane = hidden unit.
// ============================================================================
__global__ __launch_bounds__(256) void boundary_kernel(
    const float* __restrict__ ao, const float* __restrict__ w1,
    const float* __restrict__ b1, const float* __restrict__ w2,
    const float* __restrict__ b2, float* __restrict__ bscore)
{
    int row  = (blockIdx.x << 3) + (threadIdx.x >> 5);
    int lane = threadIdx.x & 31;
    const float4* a = (const float4*)(ao + (size_t)row * NE);
    const float4* w = (const float4*)(w1 + lane * NE);
    float acc = 0.f;
#pragma unroll 16
    for (int d = 0; d < 64; d++) {
        float4 av = a[d], wv = w[d];
        acc += av.x*wv.x + av.y*wv.y + av.z*wv.z + av.w*wv.w;
    }
    float hh = fmaxf(acc + b1[lane], 0.f);
    float s = hh * w2[lane];
#pragma unroll
    for (int off = 16; off; off >>= 1)
        s += __shfl_xor_sync(0xffffffffu, s, off);
    if (lane == 0)
        bscore[row] = 1.f / (1.f + expf(-(s + b2[0])));
}

// ============================================================================
// Per-batch inclusive cumsum (double) -> normalized -> patch ids.
// ============================================================================
__global__ __launch_bounds__(1024) void scan_kernel(
    const float* __restrict__ bscore, int* __restrict__ pid)
{
    __shared__ double sa[1024], sb[1024];
    int b = blockIdx.x, t = threadIdx.x;
    sa[t] = (double)bscore[b*NT + t];
    __syncthreads();
    double* src = sa; double* dst = sb;
#pragma unroll
    for (int off = 1; off < 1024; off <<= 1) {
        double v = src[t];
        if (t >= off) v += src[t - off];
        dst[t] = v;
        __syncthreads();
        double* tmp = src; src = dst; dst = tmp;
    }
    double total = src[1023] + 1e-6;
    double cbp = src[t] / total;
    int p = (int)floor(cbp * (double)NP);
    if (p > NP-1) p = NP-1;
    if (p < 0) p = 0;
    pid[b*NT + t] = p;
}

__device__ __forceinline__ int lower_bound_dev(const int* a, int n, int key) {
    int lo = 0, hi = n;
    while (lo < hi) { int mid = (lo + hi) >> 1; if (a[mid] < key) lo = mid + 1; else hi = mid; }
    return lo;
}

// ============================================================================
// Segment-mean pooling; pid monotone -> contiguous ranges, no atomics.
// ============================================================================
__global__ __launch_bounds__(256) void pool_kernel(
    const float* __restrict__ ao, const int* __restrict__ pid,
    float* __restrict__ pe)
{
    int bp = blockIdx.x;
    int b = bp >> 5, p = bp & 31;
    const int* pa = pid + b*NT;
    int s = lower_bound_dev(pa, NT, p);
    int e = lower_bound_dev(pa, NT, p+1);
    float inv = 1.f / (float)((e - s) > 0 ? (e - s) : 1);
    int col = threadIdx.x;
    float sum = 0.f;
    for (int t = s; t < e; t++)
        sum += ao[((size_t)(b*NT) + t) * NE + col];
    pe[(size_t)bp * NE + col] = sum * inv;
}

// ============================================================================
extern "C" void kernel_launch(void* const* d_in, const int* in_sizes, int n_in,
                              void* d_out, int out_size)
{
    (void)in_sizes; (void)n_in; (void)out_size;
    const float* x        = (const float*)d_in[0];
    const float* ip_w     = (const float*)d_in[1];
    const float* ip_b     = (const float*)d_in[2];
    const float* inproj_w = (const float*)d_in[3];
    const float* inproj_b = (const float*)d_in[4];
    const float* out_w    = (const float*)d_in[5];
    const float* out_b    = (const float*)d_in[6];
    const float* bp_w1    = (const float*)d_in[7];
    const float* bp_b1    = (const float*)d_in[8];
    const float* bp_w2    = (const float*)d_in[9];
    const float* bp_b2    = (const float*)d_in[10];
    const float* pr_w     = (const float*)d_in[11];
    const float* pr_b     = (const float*)d_in[12];
    float* out = (float*)d_out;

    void* p;
    float *h, *qkv, *ctx, *ao, *bs, *pe; int* pid;
    cudaGetSymbolAddress(&p, g_h);   h   = (float*)p;
    cudaGetSymbolAddress(&p, g_qkv); qkv = (float*)p;
    cudaGetSymbolAddress(&p, g_ctx); ctx = (float*)p;
    cudaGetSymbolAddress(&p, g_ao);  ao  = (float*)p;
    cudaGetSymbolAddress(&p, g_bs);  bs  = (float*)p;
    cudaGetSymbolAddress(&p, g_pid); pid = (int*)p;
    cudaGetSymbolAddress(&p, g_pe);  pe  = (float*)p;

    dim3 blk(256);
    // 1) input projection: [32768,32] -> [32768,256]
    gemm_bias_kernel<<<dim3(NE/128, NM/128), blk>>>(x, ip_w, ip_b, h, NE, 32);
    // 2) qkv projection: [32768,256] -> [32768,768]
    gemm_bias_kernel<<<dim3(3*NE/128, NM/128), blk>>>(h, inproj_w, inproj_b, qkv, 3*NE, NE);
    // 3) attention -> ctx
    flash_kernel<<<dim3(NT/64, NB*NH), blk>>>(qkv, ctx);
    // 4) out projection
    gemm_bias_kernel<<<dim3(NE/128, NM/128), blk>>>(ctx, out_w, out_b, ao, NE, NE);
    // 5) boundary scores
    boundary_kernel<<<NM/8, blk>>>(ao, bp_w1, bp_b1, bp_w2, bp_b2, bs);
    // 6) cumsum + patch ids
    scan_kernel<<<NB, NT>>>(bs, pid);
    // 7) segment-mean pooling
    pool_kernel<<<NB*NP, NE>>>(ao, pid, pe);
    // 8) patch projection -> output [32,32,256]
    gemm_bias_kernel<<<dim3(NE/128, (NB*NP)/128), blk>>>(pe, pr_w, pr_b, out, NE, NE);
}

// round 4
// speedup vs baseline: 1.3491x; 1.3491x over previous
#include <cuda_runtime.h>
#include <math.h>
#include <cstdint>

#define NB 32
#define NT 1024
#define NE 256
#define NH 4
#define NHD 64
#define NP 32
#define NM (NB*NT)

// ---- scratch (static device globals; no runtime allocation) ----
__device__ float g_h  [(size_t)NM*NE];
__device__ float g_qkv[(size_t)NM*3*NE];
__device__ float g_ctx[(size_t)NM*NE];
__device__ float g_ao [(size_t)NM*NE];
__device__ float g_bs [NM];
__device__ int   g_pid[NM];
__device__ float g_pe [NB*NP*NE];

// ============================================================================
// mma.sync tf32 helpers (baseline PTX -> works on sm_103 target)
// ============================================================================
__device__ __forceinline__ float tf32_rna(float x) {
    float r; asm("cvt.rna.tf32.f32 %0, %1;" : "=f"(r) : "f"(x)); return r;
}
// split fp32 into tf32-hi (rounded) + fp32 residual (hw truncates residual to tf32)
__device__ __forceinline__ void split_tf32(float x, uint32_t& hi, uint32_t& lo) {
    float h = tf32_rna(x);
    hi = __float_as_uint(h);
    lo = __float_as_uint(x - h);
}
// D += A(m16k8) * B(k8n8);  A row-major frag (4 regs), B col-major frag (2 regs)
__device__ __forceinline__ void mma_tf32(float* d, const uint32_t* a, const uint32_t* b) {
    asm volatile(
        "mma.sync.aligned.m16n8k8.row.col.f32.tf32.tf32.f32 "
        "{%0,%1,%2,%3}, {%4,%5,%6,%7}, {%8,%9}, {%0,%1,%2,%3};"
        : "+f"(d[0]), "+f"(d[1]), "+f"(d[2]), "+f"(d[3])
        : "r"(a[0]), "r"(a[1]), "r"(a[2]), "r"(a[3]), "r"(b[0]), "r"(b[1]));
}

// ============================================================================
// C[M,N] = A[M,K] @ W[N,K]^T + bias, tf32x3 tensor-core GEMM.
// 128x128 tile, BK=16, 256 threads = 8 warps (2m x 4n), warp tile 64x32.
// M%128==0, N%128==0, K%16==0.
// ============================================================================
__global__ __launch_bounds__(256) void gemm_mma_kernel(
    const float* __restrict__ A, const float* __restrict__ W,
    const float* __restrict__ bias, float* __restrict__ C,
    int Ndim, int Kdim)
{
    __shared__ float sA[128*20];   // raw fp32, stride 20 (conflict-free frags)
    __shared__ float sB[128*20];

    const int tid  = threadIdx.x;
    const int wid  = tid >> 5;
    const int lane = tid & 31;
    const int g    = lane >> 2;      // groupID 0..7
    const int tig  = lane & 3;       // thread-in-group 0..3
    const int wm   = wid >> 2;       // 0..1
    const int wn   = wid & 3;        // 0..3
    const int bm   = blockIdx.y << 7;
    const int bn   = blockIdx.x << 7;

    float c[4][4][4];
#pragma unroll
    for (int mi = 0; mi < 4; mi++)
#pragma unroll
        for (int nj = 0; nj < 4; nj++)
#pragma unroll
            for (int r = 0; r < 4; r++) c[mi][nj][r] = 0.f;

    const int row  = tid >> 1;
    const int half = tid & 1;
    const float* Ap = A + (size_t)(bm + row) * Kdim + half*8;
    const float* Wp = W + (size_t)(bn + row) * Kdim + half*8;
    float* sAr = sA + row*20 + half*8;
    float* sBr = sB + row*20 + half*8;

    for (int k0 = 0; k0 < Kdim; k0 += 16) {
        __syncthreads();
        *(float4*)(sAr)     = *(const float4*)(Ap + k0);
        *(float4*)(sAr + 4) = *(const float4*)(Ap + k0 + 4);
        *(float4*)(sBr)     = *(const float4*)(Wp + k0);
        *(float4*)(sBr + 4) = *(const float4*)(Wp + k0 + 4);
        __syncthreads();

#pragma unroll
        for (int kf = 0; kf < 2; kf++) {
            const int kb = kf * 8;
            uint32_t ahi[4][4], alo[4][4];
#pragma unroll
            for (int mi = 0; mi < 4; mi++) {
                const int r0 = wm*64 + mi*16;
                float a0 = sA[(r0 + g    )*20 + kb + tig];
                float a1 = sA[(r0 + g + 8)*20 + kb + tig];
                float a2 = sA[(r0 + g    )*20 + kb + tig + 4];
                float a3 = sA[(r0 + g + 8)*20 + kb + tig + 4];
                split_tf32(a0, ahi[mi][0], alo[mi][0]);
                split_tf32(a1, ahi[mi][1], alo[mi][1]);
                split_tf32(a2, ahi[mi][2], alo[mi][2]);
                split_tf32(a3, ahi[mi][3], alo[mi][3]);
            }
            uint32_t bhi[4][2], blo[4][2];
#pragma unroll
            for (int nj = 0; nj < 4; nj++) {
                const int r0 = wn*32 + nj*8;
                float b0 = sB[(r0 + g)*20 + kb + tig];
                float b1 = sB[(r0 + g)*20 + kb + tig + 4];
                split_tf32(b0, bhi[nj][0], blo[nj][0]);
                split_tf32(b1, bhi[nj][1], blo[nj][1]);
            }
#pragma unroll
            for (int mi = 0; mi < 4; mi++)
#pragma unroll
                for (int nj = 0; nj < 4; nj++) {
                    mma_tf32(c[mi][nj], ahi[mi], bhi[nj]);
                    mma_tf32(c[mi][nj], ahi[mi], blo[nj]);
                    mma_tf32(c[mi][nj], alo[mi], bhi[nj]);
                }
        }
    }

#pragma unroll
    for (int mi = 0; mi < 4; mi++) {
#pragma unroll
        for (int nj = 0; nj < 4; nj++) {
            const int cc = bn + wn*32 + nj*8 + 2*tig;
            const int r0 = bm + wm*64 + mi*16 + g;
            float2 bb = *(const float2*)(bias + cc);
            *(float2*)(C + (size_t)r0 * Ndim + cc) =
                make_float2(c[mi][nj][0] + bb.x, c[mi][nj][1] + bb.y);
            *(float2*)(C + (size_t)(r0 + 8) * Ndim + cc) =
                make_float2(c[mi][nj][2] + bb.x, c[mi][nj][3] + bb.y);
        }
    }
}

// ============================================================================
// Flash attention with tf32x3 mma. One block = (b,h) x 64 query rows.
// 128 threads = 4 warps; warp w owns q-rows 16w..16w+15. BKV=32, HD=64.
// Q kept as persistent hi/lo fragments in registers.
// ============================================================================
__global__ __launch_bounds__(128) void flash_mma_kernel(
    const float* __restrict__ qkv, float* __restrict__ ctx)
{
    __shared__ float sK [32*68];   // [key][d]   raw fp32
    __shared__ float sVT[64*36];   // [d][key]   raw fp32 (transposed)
    __shared__ float sP [64*36];   // [qrow][key] probabilities

    const int tid  = threadIdx.x;
    const int w    = tid >> 5;
    const int lane = tid & 31;
    const int g    = lane >> 2;
    const int tig  = lane & 3;

    const int qb = blockIdx.x;
    const int bh = blockIdx.y;
    const int b  = bh >> 2, h = bh & 3;

    const float* base = qkv + (size_t)b * NT * (3*NE);
    const int koff = NE + h*NHD;
    const int voff = 2*NE + h*NHD;
    const int qoff = h*NHD;
    const int qstart = qb << 6;

    // ---- persistent Q fragments (prescaled by 1/sqrt(64)=0.125) ----
    uint32_t qhi[8][4], qlo[8][4];
    {
        const size_t r0 = (size_t)(qstart + 16*w + g) * (3*NE) + qoff;
        const size_t r1 = (size_t)(qstart + 16*w + g + 8) * (3*NE) + qoff;
#pragma unroll
        for (int kf = 0; kf < 8; kf++) {
            float a0 = __ldg(base + r0 + 8*kf + tig)     * 0.125f;
            float a1 = __ldg(base + r1 + 8*kf + tig)     * 0.125f;
            float a2 = __ldg(base + r0 + 8*kf + tig + 4) * 0.125f;
            float a3 = __ldg(base + r1 + 8*kf + tig + 4) * 0.125f;
            split_tf32(a0, qhi[kf][0], qlo[kf][0]);
            split_tf32(a1, qhi[kf][1], qlo[kf][1]);
            split_tf32(a2, qhi[kf][2], qlo[kf][2]);
            split_tf32(a3, qhi[kf][3], qlo[kf][3]);
        }
    }

    float o[8][4];
#pragma unroll
    for (int j = 0; j < 8; j++)
#pragma unroll
        for (int r = 0; r < 4; r++) o[j][r] = 0.f;
    float m0 = -1e30f, m1 = -1e30f, l0 = 0.f, l1 = 0.f;

    for (int kb = 0; kb < 32; kb++) {
        __syncthreads();   // previous PV done with sVT / sK reusable
        // load K tile [32 keys][64 d]
        {
            const int r  = tid >> 2;
            const int c0 = (tid & 3) * 16;
            const float* gp = base + (size_t)(kb*32 + r)*(3*NE) + koff + c0;
            float* sp = sK + r*68 + c0;
#pragma unroll
            for (int i = 0; i < 4; i++)
                *(float4*)(sp + 4*i) = *(const float4*)(gp + 4*i);
        }
        // load V tile transposed -> sVT[d][key]
        {
            const int r  = tid & 31;
            const int c0 = (tid >> 5) * 16;
            const float* gp = base + (size_t)(kb*32 + r)*(3*NE) + voff + c0;
#pragma unroll
            for (int i = 0; i < 4; i++) {
                float4 v = *(const float4*)(gp + 4*i);
                sVT[(c0 + 4*i + 0)*36 + r] = v.x;
                sVT[(c0 + 4*i + 1)*36 + r] = v.y;
                sVT[(c0 + 4*i + 2)*36 + r] = v.z;
                sVT[(c0 + 4*i + 3)*36 + r] = v.w;
            }
        }
        __syncthreads();

        // ---- S = Q K^T (64 x 32 per block; this warp: 16 x 32) ----
        float s[4][4];
#pragma unroll
        for (int j = 0; j < 4; j++)
#pragma unroll
            for (int r = 0; r < 4; r++) s[j][r] = 0.f;
#pragma unroll
        for (int kf = 0; kf < 8; kf++) {
#pragma unroll
            for (int j = 0; j < 4; j++) {
                uint32_t bh2[2], bl2[2];
                float b0 = sK[(8*j + g)*68 + 8*kf + tig];
                float b1 = sK[(8*j + g)*68 + 8*kf + tig + 4];
                split_tf32(b0, bh2[0], bl2[0]);
                split_tf32(b1, bh2[1], bl2[1]);
                mma_tf32(s[j], qhi[kf], bh2);
                mma_tf32(s[j], qhi[kf], bl2);
                mma_tf32(s[j], qlo[kf], bh2);
            }
        }

        // ---- online softmax (rows g and g+8 of this warp) ----
        float mx0 = s[0][0], mx1 = s[0][2];
#pragma unroll
        for (int j = 0; j < 4; j++) {
            mx0 = fmaxf(mx0, fmaxf(s[j][0], s[j][1]));
            mx1 = fmaxf(mx1, fmaxf(s[j][2], s[j][3]));
        }
        mx0 = fmaxf(mx0, __shfl_xor_sync(0xffffffffu, mx0, 1));
        mx0 = fmaxf(mx0, __shfl_xor_sync(0xffffffffu, mx0, 2));
        mx1 = fmaxf(mx1, __shfl_xor_sync(0xffffffffu, mx1, 1));
        mx1 = fmaxf(mx1, __shfl_xor_sync(0xffffffffu, mx1, 2));
        float mn0 = fmaxf(m0, mx0), mn1 = fmaxf(m1, mx1);
        float corr0 = __expf(m0 - mn0), corr1 = __expf(m1 - mn1);
        m0 = mn0; m1 = mn1;

        float p[4][4];
        float sum0 = 0.f, sum1 = 0.f;
#pragma unroll
        for (int j = 0; j < 4; j++) {
            p[j][0] = __expf(s[j][0] - mn0);
            p[j][1] = __expf(s[j][1] - mn0);
            p[j][2] = __expf(s[j][2] - mn1);
            p[j][3] = __expf(s[j][3] - mn1);
            sum0 += p[j][0] + p[j][1];
            sum1 += p[j][2] + p[j][3];
        }
        sum0 += __shfl_xor_sync(0xffffffffu, sum0, 1);
        sum0 += __shfl_xor_sync(0xffffffffu, sum0, 2);
        sum1 += __shfl_xor_sync(0xffffffffu, sum1, 1);
        sum1 += __shfl_xor_sync(0xffffffffu, sum1, 2);
        l0 = l0*corr0 + sum0;
        l1 = l1*corr1 + sum1;

        // rescale O accumulators
#pragma unroll
        for (int j = 0; j < 8; j++) {
            o[j][0] *= corr0; o[j][1] *= corr0;
            o[j][2] *= corr1; o[j][3] *= corr1;
        }

        // store P to smem (own warp's rows only)
        {
            float* pr0 = sP + (16*w + g    )*36;
            float* pr1 = sP + (16*w + g + 8)*36;
#pragma unroll
            for (int j = 0; j < 4; j++) {
                *(float2*)(pr0 + 8*j + 2*tig) = make_float2(p[j][0], p[j][1]);
                *(float2*)(pr1 + 8*j + 2*tig) = make_float2(p[j][2], p[j][3]);
            }
        }
        __syncwarp();

        // ---- O += P V (16 x 64 per warp) ----
#pragma unroll
        for (int kf = 0; kf < 4; kf++) {
            uint32_t phi[4], plo[4];
            float a0 = sP[(16*w + g    )*36 + 8*kf + tig];
            float a1 = sP[(16*w + g + 8)*36 + 8*kf + tig];
            float a2 = sP[(16*w + g    )*36 + 8*kf + tig + 4];
            float a3 = sP[(16*w + g + 8)*36 + 8*kf + tig + 4];
            split_tf32(a0, phi[0], plo[0]);
            split_tf32(a1, phi[1], plo[1]);
            split_tf32(a2, phi[2], plo[2]);
            split_tf32(a3, phi[3], plo[3]);
#pragma unroll
            for (int j = 0; j < 8; j++) {
                uint32_t vh[2], vl[2];
                float b0 = sVT[(8*j + g)*36 + 8*kf + tig];
                float b1 = sVT[(8*j + g)*36 + 8*kf + tig + 4];
                split_tf32(b0, vh[0], vl[0]);
                split_tf32(b1, vh[1], vl[1]);
                mma_tf32(o[j], phi, vh);
                mma_tf32(o[j], phi, vl);
                mma_tf32(o[j], plo, vh);
            }
        }
    }

    // ---- finalize: divide by l, write ctx ----
    const float inv0 = 1.f / l0, inv1 = 1.f / l1;
    float* c0 = ctx + ((size_t)(b*NT) + qstart + 16*w + g    ) * NE + h*NHD;
    float* c1 = ctx + ((size_t)(b*NT) + qstart + 16*w + g + 8) * NE + h*NHD;
#pragma unroll
    for (int j = 0; j < 8; j++) {
        *(float2*)(c0 + 8*j + 2*tig) = make_float2(o[j][0]*inv0, o[j][1]*inv0);
        *(float2*)(c1 + 8*j + 2*tig) = make_float2(o[j][2]*inv1, o[j][3]*inv1);
    }
}

// ============================================================================
// Boundary MLP: one warp per row, lane = hidden unit.
// ============================================================================
__global__ __launch_bounds__(256) void boundary_kernel(
    const float* __restrict__ ao, const float* __restrict__ w1,
    const float* __restrict__ b1, const float* __restrict__ w2,
    const float* __restrict__ b2, float* __restrict__ bscore)
{
    int row  = (blockIdx.x << 3) + (threadIdx.x >> 5);
    int lane = threadIdx.x & 31;
    const float4* a = (const float4*)(ao + (size_t)row * NE);
    const float4* w = (const float4*)(w1 + lane * NE);
    float acc = 0.f;
#pragma unroll 16
    for (int d = 0; d < 64; d++) {
        float4 av = a[d], wv = w[d];
        acc += av.x*wv.x + av.y*wv.y + av.z*wv.z + av.w*wv.w;
    }
    float hh = fmaxf(acc + b1[lane], 0.f);
    float s = hh * w2[lane];
#pragma unroll
    for (int off = 16; off; off >>= 1)
        s += __shfl_xor_sync(0xffffffffu, s, off);
    if (lane == 0)
        bscore[row] = 1.f / (1.f + expf(-(s + b2[0])));
}

// ============================================================================
// Per-batch inclusive cumsum (double) -> normalized -> patch ids.
// ============================================================================
__global__ __launch_bounds__(1024) void scan_kernel(
    const float* __restrict__ bscore, int* __restrict__ pid)
{
    __shared__ double sa[1024], sb[1024];
    int b = blockIdx.x, t = threadIdx.x;
    sa[t] = (double)bscore[b*NT + t];
    __syncthreads();
    double* src = sa; double* dst = sb;
#pragma unroll
    for (int off = 1; off < 1024; off <<= 1) {
        double v = src[t];
        if (t >= off) v += src[t - off];
        dst[t] = v;
        __syncthreads();
        double* tmp = src; src = dst; dst = tmp;
    }
    double total = src[1023] + 1e-6;
    double cbp = src[t] / total;
    int p = (int)floor(cbp * (double)NP);
    if (p > NP-1) p = NP-1;
    if (p < 0) p = 0;
    pid[b*NT + t] = p;
}

__device__ __forceinline__ int lower_bound_dev(const int* a, int n, int key) {
    int lo = 0, hi = n;
    while (lo < hi) { int mid = (lo + hi) >> 1; if (a[mid] < key) lo = mid + 1; else hi = mid; }
    return lo;
}

// ============================================================================
// Segment-mean pooling; pid monotone -> contiguous ranges, no atomics.
// ============================================================================
__global__ __launch_bounds__(256) void pool_kernel(
    const float* __restrict__ ao, const int* __restrict__ pid,
    float* __restrict__ pe)
{
    int bp = blockIdx.x;
    int b = bp >> 5, p = bp & 31;
    const int* pa = pid + b*NT;
    int s = lower_bound_dev(pa, NT, p);
    int e = lower_bound_dev(pa, NT, p+1);
    float inv = 1.f / (float)((e - s) > 0 ? (e - s) : 1);
    int col = threadIdx.x;
    float sum = 0.f;
    for (int t = s; t < e; t++)
        sum += ao[((size_t)(b*NT) + t) * NE + col];
    pe[(size_t)bp * NE + col] = sum * inv;
}

// ============================================================================
extern "C" void kernel_launch(void* const* d_in, const int* in_sizes, int n_in,
                              void* d_out, int out_size)
{
    (void)in_sizes; (void)n_in; (void)out_size;
    const float* x        = (const float*)d_in[0];
    const float* ip_w     = (const float*)d_in[1];
    const float* ip_b     = (const float*)d_in[2];
    const float* inproj_w = (const float*)d_in[3];
    const float* inproj_b = (const float*)d_in[4];
    const float* out_w    = (const float*)d_in[5];
    const float* out_b    = (const float*)d_in[6];
    const float* bp_w1    = (const float*)d_in[7];
    const float* bp_b1    = (const float*)d_in[8];
    const float* bp_w2    = (const float*)d_in[9];
    const float* bp_b2    = (const float*)d_in[10];
    const float* pr_w     = (const float*)d_in[11];
    const float* pr_b     = (const float*)d_in[12];
    float* out = (float*)d_out;

    void* p;
    float *h, *qkv, *ctx, *ao, *bs, *pe; int* pid;
    cudaGetSymbolAddress(&p, g_h);   h   = (float*)p;
    cudaGetSymbolAddress(&p, g_qkv); qkv = (float*)p;
    cudaGetSymbolAddress(&p, g_ctx); ctx = (float*)p;
    cudaGetSymbolAddress(&p, g_ao);  ao  = (float*)p;
    cudaGetSymbolAddress(&p, g_bs);  bs  = (float*)p;
    cudaGetSymbolAddress(&p, g_pid); pid = (int*)p;
    cudaGetSymbolAddress(&p, g_pe);  pe  = (float*)p;

    dim3 blk(256);
    // 1) input projection: [32768,32] -> [32768,256]  (K=32)
    gemm_mma_kernel<<<dim3(NE/128, NM/128), blk>>>(x, ip_w, ip_b, h, NE, 32);
    // 2) qkv projection: [32768,256] -> [32768,768]
    gemm_mma_kernel<<<dim3(3*NE/128, NM/128), blk>>>(h, inproj_w, inproj_b, qkv, 3*NE, NE);
    // 3) attention -> ctx
    flash_mma_kernel<<<dim3(NT/64, NB*NH), dim3(128)>>>(qkv, ctx);
    // 4) out projection
    gemm_mma_kernel<<<dim3(NE/128, NM/128), blk>>>(ctx, out_w, out_b, ao, NE, NE);
    // 5) boundary scores
    boundary_kernel<<<NM/8, blk>>>(ao, bp_w1, bp_b1, bp_w2, bp_b2, bs);
    // 6) cumsum + patch ids
    scan_kernel<<<NB, NT>>>(bs, pid);
    // 7) segment-mean pooling
    pool_kernel<<<NB*NP, NE>>>(ao, pid, pe);
    // 8) patch projection -> output [32,32,256]
    gemm_mma_kernel<<<dim3(NE/128, (NB*NP)/128), blk>>>(pe, pr_w, pr_b, out, NE, NE);
}